// round 9
// baseline (speedup 1.0000x reference)
#include <cuda_runtime.h>
#include <math.h>

// Dataset-fixed shapes: r is [16, 2048, 3] fp32
#define NPTS    1024              // points per MST problem
#define NPROB   32                // independent MST problems
#define THREADS 128               // 4 warps: one per SMSP (full issue rate)
#define PPT     (NPTS / THREADS)  // 8 points per thread
#define NW      (THREADS / 32)    // 4 warps

__device__ float    g_partials[NPROB];
__device__ unsigned g_ticket;     // zero-init; last CTA resets for graph replay

__device__ __forceinline__ float warp_sum(float v) {
#pragma unroll
    for (int o = 16; o; o >>= 1) v += __shfl_xor_sync(0xffffffffu, v, o);
    return v;
}

__device__ __forceinline__ unsigned um(unsigned a, unsigned b) { return a < b ? a : b; }

// Pack: high 22 bits = float bits of h = d^2/2 (low 10 mantissa bits truncated),
// low 10 bits = point index. Unsigned order == (h, idx) order (h >= 0).
// pk values are globally unique within a problem (index embedded).
#define PK_MASK 0xFFFFFC00u

__global__ __launch_bounds__(THREADS, 1)
void topo_mst_kernel(const float* __restrict__ r, float* __restrict__ out)
{
    __shared__ float4 pts[NPTS];                    // {x, y, z, q=|p|^2/2}
    __shared__ float redbuf[3][NW];
    // Sync-free exchange: [buffer][warp] = {wm (hi 32), tag (lo 32)}.
    // One aligned STS.64 per warp per iteration; readers spin on the tag.
    __shared__ alignas(16) unsigned long long s_slot[2][NW];
    __shared__ bool s_last;

    const int tid  = threadIdx.x;
    const int lane = tid & 31;
    const int wid  = tid >> 5;

    const float* base = r + (size_t)blockIdx.x * NPTS * 3;

    // ---- Load (thread t owns points t, t+128, ..., t+896) ----
    float lx[PPT], ly[PPT], lz[PPT];
    float sx = 0.f, sy = 0.f, sz = 0.f;
#pragma unroll
    for (int s = 0; s < PPT; s++) {
        int i = tid + s * THREADS;
        float x = base[3 * i + 0];
        float y = base[3 * i + 1];
        float z = base[3 * i + 2];
        lx[s] = x; ly[s] = y; lz[s] = z;
        sx += x; sy += y; sz += z;
    }

    // ---- Mean ----
    sx = warp_sum(sx); sy = warp_sum(sy); sz = warp_sum(sz);
    if (lane == 0) { redbuf[0][wid] = sx; redbuf[1][wid] = sy; redbuf[2][wid] = sz; }
    __syncthreads();
    float mx = 0.f, my = 0.f, mz = 0.f;
#pragma unroll
    for (int w = 0; w < NW; w++) { mx += redbuf[0][w]; my += redbuf[1][w]; mz += redbuf[2][w]; }
    mx *= (1.0f / NPTS); my *= (1.0f / NPTS); mz *= (1.0f / NPTS);
    __syncthreads();

    // ---- Variance ----
    float vx = 0.f, vy = 0.f, vz = 0.f;
#pragma unroll
    for (int s = 0; s < PPT; s++) {
        float dx = lx[s] - mx, dy = ly[s] - my, dz = lz[s] - mz;
        vx = fmaf(dx, dx, vx); vy = fmaf(dy, dy, vy); vz = fmaf(dz, dz, vz);
    }
    vx = warp_sum(vx); vy = warp_sum(vy); vz = warp_sum(vz);
    if (lane == 0) { redbuf[0][wid] = vx; redbuf[1][wid] = vy; redbuf[2][wid] = vz; }
    __syncthreads();
    vx = 0.f; vy = 0.f; vz = 0.f;
#pragma unroll
    for (int w = 0; w < NW; w++) { vx += redbuf[0][w]; vy += redbuf[1][w]; vz += redbuf[2][w]; }
    const float inx = 1.0f / (sqrtf(vx * (1.0f / NPTS)) + 1e-8f);
    const float iny = 1.0f / (sqrtf(vy * (1.0f / NPTS)) + 1e-8f);
    const float inz = 1.0f / (sqrtf(vz * (1.0f / NPTS)) + 1e-8f);

    // ---- Normalize; q = |p|^2/2; shared float4 {x,y,z,q} ----
    float ql[PPT];
#pragma unroll
    for (int s = 0; s < PPT; s++) {
        int i = tid + s * THREADS;
        float x = (lx[s] - mx) * inx;
        float y = (ly[s] - my) * iny;
        float z = (lz[s] - mz) * inz;
        lx[s] = x; ly[s] = y; lz[s] = z;
        ql[s] = 0.5f * fmaf(x, x, fmaf(y, y, z * z));
        pts[i] = make_float4(x, y, z, ql[s]);
    }
    // init exchange slots (tag 0 < first tag 1)
    if (tid < 2 * NW) ((unsigned long long*)s_slot)[tid] = 0ull;
    __syncthreads();

    // ---- Prim init (h = d^2/2 = q_s + q_j - p.pj) ----
    const float    INF_F   = __int_as_float(0x7f800000);
    const unsigned VISITED = 0xFFFFFFFFu;

    float4 p0 = pts[0];
    unsigned pk[PPT];
#pragma unroll
    for (int s = 0; s < PPT; s++) {
        float h = fmaf(-lx[s], p0.x, fmaf(-ly[s], p0.y, fmaf(-lz[s], p0.z, ql[s] + p0.w)));
        pk[s] = (__float_as_uint(h) & PK_MASK) | (unsigned)(tid + s * THREADS);
    }
    if (tid == 0) {     // root visited: INF q forces its future h = +inf
        pk[0] = VISITED;
        ql[0] = INF_F;
    }

    volatile unsigned long long* vslot = &s_slot[0][0];

    float total = 0.0f;   // accumulates h (= d^2/2); doubled at the end
    for (int it = 0; it < NPTS - 1; ++it) {
        const int buf = it & 1;
        const unsigned tag = (unsigned)(it + 1);

        // thread-local min: 7 IMNMX (depth 3); REDUX carries value AND index
        unsigned m0 = um(pk[0], pk[1]), m1 = um(pk[2], pk[3]);
        unsigned m2 = um(pk[4], pk[5]), m3 = um(pk[6], pk[7]);
        unsigned lm = um(um(m0, m1), um(m2, m3));
        unsigned wm = __reduce_min_sync(0xffffffffu, lm);

        // publish: single aligned STS.64 {wm, tag} — atomic as one access
        if (lane == 0)
            vslot[buf * NW + wid] = ((unsigned long long)wm << 32) | (unsigned long long)tag;

        // consume: poll all 4 slots until tags match this iteration
        unsigned long long v0, v1, v2, v3;
        do {
            v0 = vslot[buf * NW + 0];
            v1 = vslot[buf * NW + 1];
            v2 = vslot[buf * NW + 2];
            v3 = vslot[buf * NW + 3];
        } while ((unsigned)v0 != tag || (unsigned)v1 != tag ||
                 (unsigned)v2 != tag || (unsigned)v3 != tag);

        // cross-warp min: 3 IMNMX on the high words (register halves, free)
        unsigned g = um(um((unsigned)(v0 >> 32), (unsigned)(v1 >> 32)),
                        um((unsigned)(v2 >> 32), (unsigned)(v3 >> 32)));

        total += __uint_as_float(g & PK_MASK);

        float4 pj = pts[g & 1023u];   // single broadcast LDS.128: {x, y, z, q_j}

        // mark visited: exactly the slot whose pk equals g (unique)
#pragma unroll
        for (int s = 0; s < PPT; s++) {
            if (pk[s] == g) { pk[s] = VISITED; ql[s] = INF_F; }
        }

        // relax: h = q_s + q_j - p.pj
#pragma unroll
        for (int s = 0; s < PPT; s++) {
            float h = fmaf(-lx[s], pj.x, fmaf(-ly[s], pj.y, fmaf(-lz[s], pj.z, ql[s] + pj.w)));
            unsigned cand = (__float_as_uint(h) & PK_MASK) | (unsigned)(tid + s * THREADS);
            pk[s] = um(pk[s], cand);
        }
    }

    // ---- deterministic finalize in the last-arriving CTA ----
    if (tid == 0) {
        g_partials[blockIdx.x] = total * 2.0f;   // h -> d^2
        __threadfence();
        unsigned t = atomicAdd(&g_ticket, 1u);
        s_last = (t == NPROB - 1);
    }
    __syncthreads();
    if (s_last && tid == 0) {
        __threadfence();
        float acc = 0.0f;
#pragma unroll
        for (int p = 0; p < NPROB; p++) acc += g_partials[p];
        out[0] = acc * (1.0f / NPROB);
        g_ticket = 0;   // reset for next graph replay
    }
}

extern "C" void kernel_launch(void* const* d_in, const int* in_sizes, int n_in,
                              void* d_out, int out_size)
{
    const float* r = (const float*)d_in[0];
    float* out = (float*)d_out;
    topo_mst_kernel<<<NPROB, THREADS>>>(r, out);
}